// round 12
// baseline (speedup 1.0000x reference)
#include <cuda_runtime.h>
#include <cuda_bf16.h>
#include <math.h>
#include <stdint.h>

#define BSZ 16
#define CDIM 512
#define HWD 1024   // 32*32

// ---------------- device scratch (allocation-guard safe) -------------------
__device__ __nv_bfloat16  g_xb [BSZ * CDIM * HWD];           // x bf16 [b][c][i]
__device__ __nv_bfloat16  g_qkv[BSZ * 3 * CDIM * HWD];       // q|k|v [b][3c][i]
__device__ __nv_bfloat16  g_ab [BSZ * HWD * HWD];            // unnormalized P bf16
__device__ __nv_bfloat16  g_ob [BSZ * CDIM * HWD];           // attn@V bf16 [b][c][i]
__device__ __nv_bfloat16  g_w  [4][CDIM * CDIM];             // Wq|Wk|Wv (1536x512), Wo
__device__ float          g_bqkv[3 * CDIM];                  // packed bq|bk|bv
__device__ float          g_part[BSZ * HWD * 16];            // row-sum partials

// ---------------- small helpers --------------------------------------------
__device__ __forceinline__ uint32_t packbf(float lo, float hi) {
    uint32_t r;
    asm("cvt.rn.bf16x2.f32 %0, %1, %2;" : "=r"(r) : "f"(hi), "f"(lo));
    return r;
}
__device__ __forceinline__ void ldm4(uint32_t r[4], uint32_t addr) {
    asm volatile("ldmatrix.sync.aligned.m8n8.x4.shared.b16 {%0,%1,%2,%3}, [%4];"
                 : "=r"(r[0]), "=r"(r[1]), "=r"(r[2]), "=r"(r[3]) : "r"(addr));
}
__device__ __forceinline__ void ldm4t(uint32_t r[4], uint32_t addr) {
    asm volatile("ldmatrix.sync.aligned.m8n8.x4.trans.shared.b16 {%0,%1,%2,%3}, [%4];"
                 : "=r"(r[0]), "=r"(r[1]), "=r"(r[2]), "=r"(r[3]) : "r"(addr));
}
__device__ __forceinline__ void mma_bf16(float c[4], const uint32_t a[4], const uint32_t b[2]) {
    asm volatile(
        "mma.sync.aligned.m16n8k16.row.col.f32.bf16.bf16.f32 "
        "{%0,%1,%2,%3}, {%4,%5,%6,%7}, {%8,%9}, {%0,%1,%2,%3};\n"
        : "+f"(c[0]), "+f"(c[1]), "+f"(c[2]), "+f"(c[3])
        : "r"(a[0]), "r"(a[1]), "r"(a[2]), "r"(a[3]), "r"(b[0]), "r"(b[1]));
}
__device__ __forceinline__ void cpa16(uint32_t dst, const void* src) {
    asm volatile("cp.async.cg.shared.global [%0], [%1], 16;" :: "r"(dst), "l"(src));
}
#define CP_COMMIT() asm volatile("cp.async.commit_group;" ::: "memory")
#define CP_WAIT1()  asm volatile("cp.async.wait_group 1;" ::: "memory")
#define CP_WAIT0()  asm volatile("cp.async.wait_group 0;" ::: "memory")

// ---------------------------------------------------------------------------
// Fused prologue: weight cvt (4x512x512), bias pack, x cvt. One launch.
// grid = 2048 blocks x 256 threads.
// ---------------------------------------------------------------------------
__global__ __launch_bounds__(256)
void prologue_kernel(const float4* __restrict__ x4,
                     const float4* __restrict__ w0, const float4* __restrict__ w1,
                     const float4* __restrict__ w2, const float4* __restrict__ w3,
                     const float* __restrict__ bq, const float* __restrict__ bk,
                     const float* __restrict__ bv,
                     uint2* __restrict__ xb, uint2* __restrict__ wdst,
                     float* __restrict__ bias)
{
    const int gid = blockIdx.x * 256 + threadIdx.x;

    if (gid < 3 * CDIM)
        bias[gid] = gid < CDIM ? bq[gid]
                  : gid < 2 * CDIM ? bk[gid - CDIM] : bv[gid - 2 * CDIM];

    if (gid < 4 * 65536) {                    // 4 mats x 65536 float4
        const int which = gid >> 16, i = gid & 65535;
        const float4* src = which == 0 ? w0 : which == 1 ? w1
                          : which == 2 ? w2 : w3;
        float4 v = src[i];
        uint2 o;
        o.x = packbf(v.x, v.y);
        o.y = packbf(v.z, v.w);
        wdst[gid] = o;
    }

    const int total = BSZ * CDIM * HWD / 4;   // 2097152 float4
    for (int i = gid; i < total; i += gridDim.x * 256) {
        float4 v = x4[i];
        uint2 o;
        o.x = packbf(v.x, v.y);
        o.y = packbf(v.z, v.w);
        xb[i] = o;
    }
}

// ---------------------------------------------------------------------------
// Batched bf16 tensor-core GEMM: C[m,n] = alpha*sum_k A[m,k]*B[k,n] (+bias)(+resid)
// CTA tile 128x128x64, 4 warps (2x2), warp tile 64x64, m16n8k16 MMAs.
// 3-stage cp.async pipeline, one __syncthreads per stage. B fragments are
// register-pipelined one 16-col block ahead.
// MODE 0: plain epilogue (OUT_F32 selects type).
// MODE 1: softmax-fused scores: C=bf16 exp(alpha*acc), aux<-row-sum partials.
// MODE 2: bf16 out scaled per-column: val *= 1/rowsum, where the rowsum is
//         reduced IN-KERNEL (post-mainloop) from aux = 16 partials per row.
// ---------------------------------------------------------------------------
template<bool A_KC, bool B_NC, int LDA, int LDB, bool BIAS, bool RESID,
         bool OUT_F32, int MODE>
__global__ __launch_bounds__(128, 2)
void gemm_bf16(const __nv_bfloat16* __restrict__ A,
               const __nv_bfloat16* __restrict__ B,
               void* __restrict__ Cv, int K,
               long baA, long baB, long baC,
               float alpha, const float* __restrict__ bias,
               const float* __restrict__ resid, long baR,
               float* __restrict__ aux)
{
    extern __shared__ uint8_t smem[];
    const uint32_t smem_u = (uint32_t)__cvta_generic_to_shared(smem);
    const int STAGE = 32768;            // 16KB A + 16KB B

    const int b = blockIdx.z;
    A += (long)b * baA;
    B += (long)b * baB;
    if (RESID) resid += (long)b * baR;

    const int tid  = threadIdx.x;
    const int lane = tid & 31;
    const int wid  = tid >> 5;          // 0..3
    const int m0   = blockIdx.y * 128;
    const int n0   = blockIdx.x * 128;
    const int wm0  = (wid >> 1) * 64;   // 0 or 64
    const int wn0  = (wid & 1) * 64;    // 0 or 64

    float acc[4][8][4];
    #pragma unroll
    for (int i = 0; i < 4; ++i)
        #pragma unroll
        for (int j = 0; j < 8; ++j)
            #pragma unroll
            for (int r = 0; r < 4; ++r) acc[i][j][r] = 0.f;

    // ---- cp.async tile fill: 1024 16B units per operand, 8 per thread ----
    auto fill = [&](int kt, int buf) {
        const int k0 = kt * 64;
        const uint32_t Ab = smem_u + buf * STAGE;
        const uint32_t Bb = Ab + 16384;
        #pragma unroll
        for (int i = 0; i < 8; ++i) {
            const int g = tid + i * 128;
            // A
            if (A_KC) {
                const int m = g >> 3, u = g & 7;
                cpa16(Ab + m * 128 + ((u ^ (m & 7)) << 4),
                      A + (long)(m0 + m) * LDA + k0 + u * 8);
            } else {
                const int kk = g >> 4, u = g & 15;
                cpa16(Ab + kk * 256 + ((u ^ (kk & 7)) << 4),
                      A + (long)(k0 + kk) * LDA + m0 + u * 8);
            }
            // B
            if (B_NC) {
                const int kk = g >> 4, u = g & 15;
                cpa16(Bb + kk * 256 + ((u ^ (kk & 7)) << 4),
                      B + (long)(k0 + kk) * LDB + n0 + u * 8);
            } else {
                const int n = g >> 3, u = g & 7;
                cpa16(Bb + n * 128 + ((u ^ (n & 7)) << 4),
                      B + (long)(n0 + n) * LDB + k0 + u * 8);
            }
        }
        CP_COMMIT();
    };

    // ---- B fragment load for one 16-col block ----
    auto loadB = [&](uint32_t Bb, int s, int tb, uint32_t r[4]) {
        if (B_NC) {
            const int k_row = s * 16 + (lane & 7) + ((lane >> 3) & 1) * 8;
            const int u = ((wn0 + tb * 16) >> 3) + ((lane >> 4) & 1);
            ldm4t(r, Bb + k_row * 256 + ((u ^ (k_row & 7)) << 4));
        } else {
            const int n_row = wn0 + tb * 16 + (lane & 7) + ((lane >> 4) & 1) * 8;
            const int u = 2 * s + ((lane >> 3) & 1);
            ldm4(r, Bb + n_row * 128 + ((u ^ (n_row & 7)) << 4));
        }
    };

    // ---- compute one 64-deep k-tile; B frags pipelined one block ahead ----
    auto compute = [&](int buf) {
        const uint32_t Ab = smem_u + buf * STAGE;
        const uint32_t Bb = Ab + 16384;
        #pragma unroll
        for (int s = 0; s < 4; ++s) {
            uint32_t af[4][4];
            #pragma unroll
            for (int tm = 0; tm < 4; ++tm) {
                if (A_KC) {
                    const int m_row = wm0 + tm * 16 + (lane & 15);
                    const int u = 2 * s + (lane >> 4);
                    ldm4(af[tm], Ab + m_row * 128 + ((u ^ (m_row & 7)) << 4));
                } else {
                    const int k_row = s * 16 + (lane & 7) + ((lane >> 4) & 1) * 8;
                    const int u = ((wm0 + tm * 16) >> 3) + ((lane >> 3) & 1);
                    ldm4t(af[tm], Ab + k_row * 256 + ((u ^ (k_row & 7)) << 4));
                }
            }
            uint32_t rb[2][4];
            loadB(Bb, s, 0, rb[0]);
            #pragma unroll
            for (int tb = 0; tb < 4; ++tb) {
                if (tb < 3) loadB(Bb, s, tb + 1, rb[(tb + 1) & 1]);
                const uint32_t* r = rb[tb & 1];
                uint32_t b0[2] = { r[0], r[1] };
                uint32_t b1[2] = { r[2], r[3] };
                #pragma unroll
                for (int tm = 0; tm < 4; ++tm) {
                    mma_bf16(acc[tm][tb * 2],     af[tm], b0);
                    mma_bf16(acc[tm][tb * 2 + 1], af[tm], b1);
                }
            }
        }
    };

    const int nkt = K >> 6;
    fill(0, 0);
    if (nkt > 1) fill(1, 1);

    for (int kt = 0; kt < nkt; ++kt) {
        if (kt == nkt - 1) { CP_WAIT0(); } else { CP_WAIT1(); }
        __syncthreads();
        // refill buffer (kt+2)%3 == (kt-1)%3: finished by ALL warps before
        // the barrier above -> safe with a single sync per stage.
        if (kt + 2 < nkt) fill(kt + 2, (kt + 2) % 3);
        compute(kt % 3);
    }

    // ---- epilogue ----
    const int kq = lane & 3;
    const int mq = lane >> 2;

    // MODE 2: reduce 16 row-sum partials -> 1/rowsum for this CTA's 128
    // columns, in smem (mainloop buffers are dead after the barrier).
    float* sinv = (float*)smem;
    if (MODE == 2) {
        __syncthreads();            // mainloop smem reads complete everywhere
        const float4* p4 = (const float4*)(aux + ((long)b * HWD + n0 + tid) * 16);
        float4 pa = p4[0], pb = p4[1], pc = p4[2], pd = p4[3];
        float ssum = (pa.x + pa.y + pa.z + pa.w) + (pb.x + pb.y + pb.z + pb.w)
                   + (pc.x + pc.y + pc.z + pc.w) + (pd.x + pd.y + pd.z + pd.w);
        sinv[tid] = 1.f / ssum;
        __syncthreads();
    }

    float invs[16];
    if (MODE == 2) {
        #pragma unroll
        for (int tn = 0; tn < 8; ++tn) {
            const int nl = wn0 + tn * 8 + 2 * kq;
            invs[tn * 2]     = sinv[nl];
            invs[tn * 2 + 1] = sinv[nl + 1];
        }
    }

    #pragma unroll
    for (int tm = 0; tm < 4; ++tm) {
        const int mA = m0 + wm0 + tm * 16 + mq;
        const int mB = mA + 8;
        if (MODE == 1) {
            // softmax-fused score epilogue: e = exp(alpha*acc), bf16 out,
            // per-row partial sums over this warp's 64 columns.
            __nv_bfloat16* C = (__nv_bfloat16*)Cv + (long)b * baC;
            float sA = 0.f, sB = 0.f;
            #pragma unroll
            for (int tn = 0; tn < 8; ++tn) {
                const int n = n0 + wn0 + tn * 8 + 2 * kq;
                float e0 = __expf(alpha * acc[tm][tn][0]);
                float e1 = __expf(alpha * acc[tm][tn][1]);
                float e2 = __expf(alpha * acc[tm][tn][2]);
                float e3 = __expf(alpha * acc[tm][tn][3]);
                sA += e0 + e1;
                sB += e2 + e3;
                *(uint32_t*)&C[(long)mA * HWD + n] = packbf(e0, e1);
                *(uint32_t*)&C[(long)mB * HWD + n] = packbf(e2, e3);
            }
            sA += __shfl_xor_sync(0xFFFFFFFFu, sA, 1);
            sA += __shfl_xor_sync(0xFFFFFFFFu, sA, 2);
            sB += __shfl_xor_sync(0xFFFFFFFFu, sB, 1);
            sB += __shfl_xor_sync(0xFFFFFFFFu, sB, 2);
            if (kq == 0) {
                const int jt2 = blockIdx.x * 2 + (wid & 1);
                aux[((long)b * HWD + mA) * 16 + jt2] = sA;
                aux[((long)b * HWD + mB) * 16 + jt2] = sB;
            }
        } else {
            const float biA = BIAS ? bias[mA] : 0.f;
            const float biB = BIAS ? bias[mB] : 0.f;
            #pragma unroll
            for (int tn = 0; tn < 8; ++tn) {
                const int n = n0 + wn0 + tn * 8 + 2 * kq;
                float v0 = alpha * acc[tm][tn][0] + biA;
                float v1 = alpha * acc[tm][tn][1] + biA;
                float v2 = alpha * acc[tm][tn][2] + biB;
                float v3 = alpha * acc[tm][tn][3] + biB;
                if (MODE == 2) {
                    v0 *= invs[tn * 2];     v1 *= invs[tn * 2 + 1];
                    v2 *= invs[tn * 2];     v3 *= invs[tn * 2 + 1];
                }
                if (RESID) {
                    const float2 rA = *(const float2*)&resid[(long)mA * HWD + n];
                    const float2 rB = *(const float2*)&resid[(long)mB * HWD + n];
                    v0 += rA.x; v1 += rA.y; v2 += rB.x; v3 += rB.y;
                }
                if (OUT_F32) {
                    float* C = (float*)Cv + (long)b * baC;
                    *(float2*)&C[(long)mA * HWD + n] = make_float2(v0, v1);
                    *(float2*)&C[(long)mB * HWD + n] = make_float2(v2, v3);
                } else {
                    __nv_bfloat16* C = (__nv_bfloat16*)Cv + (long)b * baC;
                    *(uint32_t*)&C[(long)mA * HWD + n] = packbf(v0, v1);
                    *(uint32_t*)&C[(long)mB * HWD + n] = packbf(v2, v3);
                }
            }
        }
    }
}

// ---------------------------------------------------------------------------
extern "C" void kernel_launch(void* const* d_in, const int* in_sizes, int n_in,
                              void* d_out, int out_size)
{
    const float* x  = (const float*)d_in[0];
    const float* Wq = (const float*)d_in[1];
    const float* bq = (const float*)d_in[2];
    const float* Wk = (const float*)d_in[3];
    const float* bk = (const float*)d_in[4];
    const float* Wv = (const float*)d_in[5];
    const float* bv = (const float*)d_in[6];
    const float* Wo = (const float*)d_in[7];
    const float* bo = (const float*)d_in[8];
    float* out = (float*)d_out;

    float *bqkv, *part;
    __nv_bfloat16 *xb, *qkv, *ab, *ob, *wbase;
    cudaGetSymbolAddress((void**)&xb,   g_xb);
    cudaGetSymbolAddress((void**)&qkv,  g_qkv);
    cudaGetSymbolAddress((void**)&ab,   g_ab);
    cudaGetSymbolAddress((void**)&ob,   g_ob);
    cudaGetSymbolAddress((void**)&wbase, g_w);
    cudaGetSymbolAddress((void**)&bqkv, g_bqkv);
    cudaGetSymbolAddress((void**)&part, g_part);
    __nv_bfloat16* wqkv = wbase;                     // Wq|Wk|Wv = [1536][512]
    __nv_bfloat16* wo   = wbase + 3 * CDIM * CDIM;

    const long CHW  = (long)CDIM * HWD;
    const long QKVB = 3 * CHW;                       // per-batch qkv stride
    const long SHW  = (long)HWD * HWD;
    const int  SMEM = 3 * 32768;
    const dim3 blk(128);

    auto kProj  = gemm_bf16<true,  true,  CDIM, HWD, true,  false, false, 0>;
    auto kScore = gemm_bf16<false, true,  HWD,  HWD, false, false, false, 1>;
    auto kAV    = gemm_bf16<true,  false, HWD,  HWD, false, false, false, 2>;
    auto kOut   = gemm_bf16<true,  true,  CDIM, HWD, true,  true,  true,  0>;
    cudaFuncSetAttribute(kProj,  cudaFuncAttributeMaxDynamicSharedMemorySize, SMEM);
    cudaFuncSetAttribute(kScore, cudaFuncAttributeMaxDynamicSharedMemorySize, SMEM);
    cudaFuncSetAttribute(kAV,    cudaFuncAttributeMaxDynamicSharedMemorySize, SMEM);
    cudaFuncSetAttribute(kOut,   cudaFuncAttributeMaxDynamicSharedMemorySize, SMEM);

    // 0) fused prologue: weight cvt + bias pack + x cvt
    prologue_kernel<<<2048, 256>>>((const float4*)x,
                                   (const float4*)Wq, (const float4*)Wk,
                                   (const float4*)Wv, (const float4*)Wo,
                                   bq, bk, bv,
                                   (uint2*)xb, (uint2*)wbase, bqkv);

    // 1) fused QKV projection: qkv[b][m][i] = sum_c Wqkv[m][c]*x[b][c][i] + bias[m]
    {
        dim3 grd(HWD / 128, 3 * CDIM / 128, BSZ);
        kProj<<<grd, blk, SMEM>>>(wqkv, xb, qkv, CDIM, 0, CHW, QKVB,
                                  1.f, bqkv, nullptr, 0, nullptr);
    }
    // 2) scores + fused exp: P[b][i][j] = exp(alpha * q.k), partial row sums
    {
        dim3 grd(HWD / 128, HWD / 128, BSZ);
        const float alpha = 1.0f / sqrtf((float)CDIM);
        kScore<<<grd, blk, SMEM>>>(qkv, qkv + CHW, ab, CDIM, QKVB, QKVB, SHW,
                                   alpha, nullptr, nullptr, 0, part);
    }
    // 3) attn @ V with fused normalization (rowsum reduced in-kernel):
    //    ob[b][c][i] = (sum_j v[b][c][j]*P[b][i][j]) / rowsum[b][i]
    {
        dim3 grd(HWD / 128, CDIM / 128, BSZ);
        kAV<<<grd, blk, SMEM>>>(qkv + 2 * CHW, ab, ob, HWD, QKVB, SHW, CHW,
                                1.f, nullptr, nullptr, 0, part);
    }
    // 4) output projection + bias + residual (fp32 out)
    {
        dim3 grd(HWD / 128, CDIM / 128, BSZ);
        kOut<<<grd, blk, SMEM>>>(wo, ob, out, CDIM, 0, CHW, CHW, 1.f,
                                 bo, x, CHW, nullptr);
    }
}

// round 15
// speedup vs baseline: 1.0473x; 1.0473x over previous
#include <cuda_runtime.h>
#include <cuda_bf16.h>
#include <math.h>
#include <stdint.h>

#define BSZ 16
#define CDIM 512
#define HWD 1024   // 32*32

// ---------------- device scratch (allocation-guard safe) -------------------
__device__ __nv_bfloat16  g_xb [BSZ * CDIM * HWD];           // x bf16 [b][c][i]
__device__ __nv_bfloat16  g_qkv[BSZ * 3 * CDIM * HWD];       // q|k|v [b][3c][i]
__device__ __nv_bfloat16  g_ab [BSZ * HWD * HWD];            // unnormalized P bf16
__device__ __nv_bfloat16  g_ob [BSZ * CDIM * HWD];           // attn@V bf16 [b][c][i]
__device__ __nv_bfloat16  g_w  [4][CDIM * CDIM];             // Wq|Wk|Wv (1536x512), Wo
__device__ float          g_bqkv[3 * CDIM];                  // packed bq|bk|bv
__device__ float          g_part[BSZ * HWD * 16];            // row-sum partials
__device__ float          g_inv [BSZ * HWD];                 // 1/rowsum

// ---------------- small helpers --------------------------------------------
__device__ __forceinline__ uint32_t packbf(float lo, float hi) {
    uint32_t r;
    asm("cvt.rn.bf16x2.f32 %0, %1, %2;" : "=r"(r) : "f"(hi), "f"(lo));
    return r;
}
__device__ __forceinline__ void ldm4(uint32_t r[4], uint32_t addr) {
    asm volatile("ldmatrix.sync.aligned.m8n8.x4.shared.b16 {%0,%1,%2,%3}, [%4];"
                 : "=r"(r[0]), "=r"(r[1]), "=r"(r[2]), "=r"(r[3]) : "r"(addr));
}
__device__ __forceinline__ void ldm4t(uint32_t r[4], uint32_t addr) {
    asm volatile("ldmatrix.sync.aligned.m8n8.x4.trans.shared.b16 {%0,%1,%2,%3}, [%4];"
                 : "=r"(r[0]), "=r"(r[1]), "=r"(r[2]), "=r"(r[3]) : "r"(addr));
}
__device__ __forceinline__ void mma_bf16(float c[4], const uint32_t a[4], const uint32_t b[2]) {
    asm volatile(
        "mma.sync.aligned.m16n8k16.row.col.f32.bf16.bf16.f32 "
        "{%0,%1,%2,%3}, {%4,%5,%6,%7}, {%8,%9}, {%0,%1,%2,%3};\n"
        : "+f"(c[0]), "+f"(c[1]), "+f"(c[2]), "+f"(c[3])
        : "r"(a[0]), "r"(a[1]), "r"(a[2]), "r"(a[3]), "r"(b[0]), "r"(b[1]));
}
__device__ __forceinline__ void cpa16(uint32_t dst, const void* src) {
    asm volatile("cp.async.cg.shared.global [%0], [%1], 16;" :: "r"(dst), "l"(src));
}
#define CP_COMMIT() asm volatile("cp.async.commit_group;" ::: "memory")
#define CP_WAIT1()  asm volatile("cp.async.wait_group 1;" ::: "memory")
#define CP_WAIT0()  asm volatile("cp.async.wait_group 0;" ::: "memory")

// ---------------------------------------------------------------------------
// Fused prologue: weight cvt (4x512x512), bias pack, x cvt. One launch.
// grid = 2048 blocks x 256 threads.
// ---------------------------------------------------------------------------
__global__ __launch_bounds__(256)
void prologue_kernel(const float4* __restrict__ x4,
                     const float4* __restrict__ w0, const float4* __restrict__ w1,
                     const float4* __restrict__ w2, const float4* __restrict__ w3,
                     const float* __restrict__ bq, const float* __restrict__ bk,
                     const float* __restrict__ bv,
                     uint2* __restrict__ xb, uint2* __restrict__ wdst,
                     float* __restrict__ bias)
{
    const int gid = blockIdx.x * 256 + threadIdx.x;

    if (gid < 3 * CDIM)
        bias[gid] = gid < CDIM ? bq[gid]
                  : gid < 2 * CDIM ? bk[gid - CDIM] : bv[gid - 2 * CDIM];

    if (gid < 4 * 65536) {                    // 4 mats x 65536 float4
        const int which = gid >> 16, i = gid & 65535;
        const float4* src = which == 0 ? w0 : which == 1 ? w1
                          : which == 2 ? w2 : w3;
        float4 v = src[i];
        uint2 o;
        o.x = packbf(v.x, v.y);
        o.y = packbf(v.z, v.w);
        wdst[gid] = o;
    }

    const int total = BSZ * CDIM * HWD / 4;   // 2097152 float4
    for (int i = gid; i < total; i += gridDim.x * 256) {
        float4 v = x4[i];
        uint2 o;
        o.x = packbf(v.x, v.y);
        o.y = packbf(v.z, v.w);
        xb[i] = o;
    }
}

// ---------------------------------------------------------------------------
// Batched bf16 tensor-core GEMM: C[m,n] = alpha*sum_k A[m,k]*B[k,n] (+bias)(+resid)
// CTA tile 128x128x64, 4 warps (2x2), warp tile 64x64, m16n8k16 MMAs.
// 3-stage cp.async pipeline, one __syncthreads per stage. B fragments are
// register-pipelined one 16-col block ahead.
// MODE 0: plain epilogue (OUT_F32 selects type).
// MODE 1: softmax-fused scores: C=bf16 exp(alpha*acc), aux<-row-sum partials.
// MODE 2: bf16 out scaled per-column: val *= aux[b*HWD + n] (1/rowsum).
// ---------------------------------------------------------------------------
template<bool A_KC, bool B_NC, int LDA, int LDB, bool BIAS, bool RESID,
         bool OUT_F32, int MODE>
__global__ __launch_bounds__(128, 2)
void gemm_bf16(const __nv_bfloat16* __restrict__ A,
               const __nv_bfloat16* __restrict__ B,
               void* __restrict__ Cv, int K,
               long baA, long baB, long baC,
               float alpha, const float* __restrict__ bias,
               const float* __restrict__ resid, long baR,
               float* __restrict__ aux)
{
    extern __shared__ uint8_t smem[];
    const uint32_t smem_u = (uint32_t)__cvta_generic_to_shared(smem);
    const int STAGE = 32768;            // 16KB A + 16KB B

    const int b = blockIdx.z;
    A += (long)b * baA;
    B += (long)b * baB;
    if (RESID) resid += (long)b * baR;

    const int tid  = threadIdx.x;
    const int lane = tid & 31;
    const int wid  = tid >> 5;          // 0..3
    const int m0   = blockIdx.y * 128;
    const int n0   = blockIdx.x * 128;
    const int wm0  = (wid >> 1) * 64;   // 0 or 64
    const int wn0  = (wid & 1) * 64;    // 0 or 64

    float acc[4][8][4];
    #pragma unroll
    for (int i = 0; i < 4; ++i)
        #pragma unroll
        for (int j = 0; j < 8; ++j)
            #pragma unroll
            for (int r = 0; r < 4; ++r) acc[i][j][r] = 0.f;

    // ---- cp.async tile fill: 1024 16B units per operand, 8 per thread ----
    auto fill = [&](int kt, int buf) {
        const int k0 = kt * 64;
        const uint32_t Ab = smem_u + buf * STAGE;
        const uint32_t Bb = Ab + 16384;
        #pragma unroll
        for (int i = 0; i < 8; ++i) {
            const int g = tid + i * 128;
            // A
            if (A_KC) {
                const int m = g >> 3, u = g & 7;
                cpa16(Ab + m * 128 + ((u ^ (m & 7)) << 4),
                      A + (long)(m0 + m) * LDA + k0 + u * 8);
            } else {
                const int kk = g >> 4, u = g & 15;
                cpa16(Ab + kk * 256 + ((u ^ (kk & 7)) << 4),
                      A + (long)(k0 + kk) * LDA + m0 + u * 8);
            }
            // B
            if (B_NC) {
                const int kk = g >> 4, u = g & 15;
                cpa16(Bb + kk * 256 + ((u ^ (kk & 7)) << 4),
                      B + (long)(k0 + kk) * LDB + n0 + u * 8);
            } else {
                const int n = g >> 3, u = g & 7;
                cpa16(Bb + n * 128 + ((u ^ (n & 7)) << 4),
                      B + (long)(n0 + n) * LDB + k0 + u * 8);
            }
        }
        CP_COMMIT();
    };

    // ---- B fragment load for one 16-col block ----
    auto loadB = [&](uint32_t Bb, int s, int tb, uint32_t r[4]) {
        if (B_NC) {
            const int k_row = s * 16 + (lane & 7) + ((lane >> 3) & 1) * 8;
            const int u = ((wn0 + tb * 16) >> 3) + ((lane >> 4) & 1);
            ldm4t(r, Bb + k_row * 256 + ((u ^ (k_row & 7)) << 4));
        } else {
            const int n_row = wn0 + tb * 16 + (lane & 7) + ((lane >> 4) & 1) * 8;
            const int u = 2 * s + ((lane >> 3) & 1);
            ldm4(r, Bb + n_row * 128 + ((u ^ (n_row & 7)) << 4));
        }
    };

    // ---- compute one 64-deep k-tile; B frags pipelined one block ahead ----
    auto compute = [&](int buf) {
        const uint32_t Ab = smem_u + buf * STAGE;
        const uint32_t Bb = Ab + 16384;
        #pragma unroll
        for (int s = 0; s < 4; ++s) {
            uint32_t af[4][4];
            #pragma unroll
            for (int tm = 0; tm < 4; ++tm) {
                if (A_KC) {
                    const int m_row = wm0 + tm * 16 + (lane & 15);
                    const int u = 2 * s + (lane >> 4);
                    ldm4(af[tm], Ab + m_row * 128 + ((u ^ (m_row & 7)) << 4));
                } else {
                    const int k_row = s * 16 + (lane & 7) + ((lane >> 4) & 1) * 8;
                    const int u = ((wm0 + tm * 16) >> 3) + ((lane >> 3) & 1);
                    ldm4t(af[tm], Ab + k_row * 256 + ((u ^ (k_row & 7)) << 4));
                }
            }
            uint32_t rb[2][4];
            loadB(Bb, s, 0, rb[0]);
            #pragma unroll
            for (int tb = 0; tb < 4; ++tb) {
                if (tb < 3) loadB(Bb, s, tb + 1, rb[(tb + 1) & 1]);
                const uint32_t* r = rb[tb & 1];
                uint32_t b0[2] = { r[0], r[1] };
                uint32_t b1[2] = { r[2], r[3] };
                #pragma unroll
                for (int tm = 0; tm < 4; ++tm) {
                    mma_bf16(acc[tm][tb * 2],     af[tm], b0);
                    mma_bf16(acc[tm][tb * 2 + 1], af[tm], b1);
                }
            }
        }
    };

    const int nkt = K >> 6;
    fill(0, 0);
    if (nkt > 1) fill(1, 1);

    for (int kt = 0; kt < nkt; ++kt) {
        if (kt == nkt - 1) { CP_WAIT0(); } else { CP_WAIT1(); }
        __syncthreads();
        // refill buffer (kt+2)%3 == (kt-1)%3: finished by ALL warps before
        // the barrier above -> safe with a single sync per stage.
        if (kt + 2 < nkt) fill(kt + 2, (kt + 2) % 3);
        compute(kt % 3);
    }

    // ---- epilogue ----
    const int kq = lane & 3;
    const int mq = lane >> 2;

    float invs[16];
    if (MODE == 2) {
        #pragma unroll
        for (int tn = 0; tn < 8; ++tn) {
            const int n = n0 + wn0 + tn * 8 + 2 * kq;
            invs[tn * 2]     = aux[(long)b * HWD + n];
            invs[tn * 2 + 1] = aux[(long)b * HWD + n + 1];
        }
    }

    #pragma unroll
    for (int tm = 0; tm < 4; ++tm) {
        const int mA = m0 + wm0 + tm * 16 + mq;
        const int mB = mA + 8;
        if (MODE == 1) {
            // softmax-fused score epilogue: e = exp(alpha*acc), bf16 out,
            // per-row partial sums over this warp's 64 columns.
            __nv_bfloat16* C = (__nv_bfloat16*)Cv + (long)b * baC;
            float sA = 0.f, sB = 0.f;
            #pragma unroll
            for (int tn = 0; tn < 8; ++tn) {
                const int n = n0 + wn0 + tn * 8 + 2 * kq;
                float e0 = __expf(alpha * acc[tm][tn][0]);
                float e1 = __expf(alpha * acc[tm][tn][1]);
                float e2 = __expf(alpha * acc[tm][tn][2]);
                float e3 = __expf(alpha * acc[tm][tn][3]);
                sA += e0 + e1;
                sB += e2 + e3;
                *(uint32_t*)&C[(long)mA * HWD + n] = packbf(e0, e1);
                *(uint32_t*)&C[(long)mB * HWD + n] = packbf(e2, e3);
            }
            sA += __shfl_xor_sync(0xFFFFFFFFu, sA, 1);
            sA += __shfl_xor_sync(0xFFFFFFFFu, sA, 2);
            sB += __shfl_xor_sync(0xFFFFFFFFu, sB, 1);
            sB += __shfl_xor_sync(0xFFFFFFFFu, sB, 2);
            if (kq == 0) {
                const int jt2 = blockIdx.x * 2 + (wid & 1);
                aux[((long)b * HWD + mA) * 16 + jt2] = sA;
                aux[((long)b * HWD + mB) * 16 + jt2] = sB;
            }
        } else {
            const float biA = BIAS ? bias[mA] : 0.f;
            const float biB = BIAS ? bias[mB] : 0.f;
            #pragma unroll
            for (int tn = 0; tn < 8; ++tn) {
                const int n = n0 + wn0 + tn * 8 + 2 * kq;
                float v0 = alpha * acc[tm][tn][0] + biA;
                float v1 = alpha * acc[tm][tn][1] + biA;
                float v2 = alpha * acc[tm][tn][2] + biB;
                float v3 = alpha * acc[tm][tn][3] + biB;
                if (MODE == 2) {
                    v0 *= invs[tn * 2];     v1 *= invs[tn * 2 + 1];
                    v2 *= invs[tn * 2];     v3 *= invs[tn * 2 + 1];
                }
                if (RESID) {
                    const float2 rA = *(const float2*)&resid[(long)mA * HWD + n];
                    const float2 rB = *(const float2*)&resid[(long)mB * HWD + n];
                    v0 += rA.x; v1 += rA.y; v2 += rB.x; v3 += rB.y;
                }
                if (OUT_F32) {
                    float* C = (float*)Cv + (long)b * baC;
                    *(float2*)&C[(long)mA * HWD + n] = make_float2(v0, v1);
                    *(float2*)&C[(long)mB * HWD + n] = make_float2(v2, v3);
                } else {
                    __nv_bfloat16* C = (__nv_bfloat16*)Cv + (long)b * baC;
                    *(uint32_t*)&C[(long)mA * HWD + n] = packbf(v0, v1);
                    *(uint32_t*)&C[(long)mB * HWD + n] = packbf(v2, v3);
                }
            }
        }
    }
}

// Reduce 16 partials per row -> 1/rowsum. 16384 rows.
__global__ __launch_bounds__(256)
void rowsum_inv_kernel(const float4* __restrict__ part, float* __restrict__ inv)
{
    const int i = blockIdx.x * 256 + threadIdx.x;   // < 16384
    float4 a = part[i * 4 + 0];
    float4 b = part[i * 4 + 1];
    float4 c = part[i * 4 + 2];
    float4 d = part[i * 4 + 3];
    float s = (a.x + a.y + a.z + a.w) + (b.x + b.y + b.z + b.w)
            + (c.x + c.y + c.z + c.w) + (d.x + d.y + d.z + d.w);
    inv[i] = 1.f / s;
}

// ---------------------------------------------------------------------------
extern "C" void kernel_launch(void* const* d_in, const int* in_sizes, int n_in,
                              void* d_out, int out_size)
{
    const float* x  = (const float*)d_in[0];
    const float* Wq = (const float*)d_in[1];
    const float* bq = (const float*)d_in[2];
    const float* Wk = (const float*)d_in[3];
    const float* bk = (const float*)d_in[4];
    const float* Wv = (const float*)d_in[5];
    const float* bv = (const float*)d_in[6];
    const float* Wo = (const float*)d_in[7];
    const float* bo = (const float*)d_in[8];
    float* out = (float*)d_out;

    float *bqkv, *part, *inv;
    __nv_bfloat16 *xb, *qkv, *ab, *ob, *wbase;
    cudaGetSymbolAddress((void**)&xb,   g_xb);
    cudaGetSymbolAddress((void**)&qkv,  g_qkv);
    cudaGetSymbolAddress((void**)&ab,   g_ab);
    cudaGetSymbolAddress((void**)&ob,   g_ob);
    cudaGetSymbolAddress((void**)&wbase, g_w);
    cudaGetSymbolAddress((void**)&bqkv, g_bqkv);
    cudaGetSymbolAddress((void**)&part, g_part);
    cudaGetSymbolAddress((void**)&inv,  g_inv);
    __nv_bfloat16* wqkv = wbase;                     // Wq|Wk|Wv = [1536][512]
    __nv_bfloat16* wo   = wbase + 3 * CDIM * CDIM;

    const long CHW  = (long)CDIM * HWD;
    const long QKVB = 3 * CHW;                       // per-batch qkv stride
    const long SHW  = (long)HWD * HWD;
    const int  SMEM = 3 * 32768;
    const dim3 blk(128);

    auto kProj  = gemm_bf16<true,  true,  CDIM, HWD, true,  false, false, 0>;
    auto kScore = gemm_bf16<false, true,  HWD,  HWD, false, false, false, 1>;
    auto kAV    = gemm_bf16<true,  false, HWD,  HWD, false, false, false, 2>;
    auto kOut   = gemm_bf16<true,  true,  CDIM, HWD, true,  true,  true,  0>;
    cudaFuncSetAttribute(kProj,  cudaFuncAttributeMaxDynamicSharedMemorySize, SMEM);
    cudaFuncSetAttribute(kScore, cudaFuncAttributeMaxDynamicSharedMemorySize, SMEM);
    cudaFuncSetAttribute(kAV,    cudaFuncAttributeMaxDynamicSharedMemorySize, SMEM);
    cudaFuncSetAttribute(kOut,   cudaFuncAttributeMaxDynamicSharedMemorySize, SMEM);

    // Fork/join plumbing: created ONCE during the (uncaptured) correctness
    // call; reused on the capture call, never destroyed. All launches and
    // event ops use stream handle 0 (the SAME default stream the harness's
    // compilation mode resolves for <<<>>> launches) so everything stays
    // inside the capture; s2 is pulled in via the fork event.
    static cudaStream_t s2 = nullptr;
    static cudaEvent_t evFork = nullptr, evJoin = nullptr;
    if (s2 == nullptr) {
        cudaStreamCreateWithFlags(&s2, cudaStreamNonBlocking);
        cudaEventCreateWithFlags(&evFork, cudaEventDisableTiming);
        cudaEventCreateWithFlags(&evJoin, cudaEventDisableTiming);
    }

    // 0) fused prologue: weight cvt + bias pack + x cvt   (default stream)
    prologue_kernel<<<2048, 256>>>((const float4*)x,
                                   (const float4*)Wq, (const float4*)Wk,
                                   (const float4*)Wv, (const float4*)Wo,
                                   bq, bk, bv,
                                   (uint2*)xb, (uint2*)wbase, bqkv);

    // Fork: stream2 depends on prologue only.
    cudaEventRecord(evFork, 0);
    cudaStreamWaitEvent(s2, evFork, 0);

    // 1a) QK projection (rows 0..1023 of Wqkv)        (default stream)
    {
        dim3 grd(HWD / 128, 2 * CDIM / 128, BSZ);
        kProj<<<grd, blk, SMEM>>>(wqkv, xb, qkv, CDIM, 0, CHW, QKVB,
                                  1.f, bqkv, nullptr, 0, nullptr);
    }
    // 1b) V projection (rows 1024..1535)              (stream 2, overlapped)
    {
        dim3 grd(HWD / 128, CDIM / 128, BSZ);
        kProj<<<grd, blk, SMEM, s2>>>(wqkv + (long)2 * CDIM * CDIM, xb,
                                      qkv + (long)2 * CDIM * HWD, CDIM,
                                      0, CHW, QKVB,
                                      1.f, bqkv + 2 * CDIM, nullptr, 0, nullptr);
    }
    // 2) scores + fused exp (default stream)
    {
        dim3 grd(HWD / 128, HWD / 128, BSZ);
        const float alpha = 1.0f / sqrtf((float)CDIM);
        kScore<<<grd, blk, SMEM>>>(qkv, qkv + CHW, ab, CDIM, QKVB, QKVB, SHW,
                                   alpha, nullptr, nullptr, 0, part);
    }
    // 3) 1/rowsum (default stream; small)
    rowsum_inv_kernel<<<BSZ * HWD / 256, 256>>>((const float4*)part, inv);

    // Join: default stream waits for V projection.
    cudaEventRecord(evJoin, s2);
    cudaStreamWaitEvent((cudaStream_t)0, evJoin, 0);

    // 4) attn @ V with fused normalization (default stream)
    {
        dim3 grd(HWD / 128, CDIM / 128, BSZ);
        kAV<<<grd, blk, SMEM>>>(qkv + 2 * CHW, ab, ob, HWD, QKVB, SHW, CHW,
                                1.f, nullptr, nullptr, 0, inv);
    }
    // 5) output projection + bias + residual (fp32 out) (default stream)
    {
        dim3 grd(HWD / 128, CDIM / 128, BSZ);
        kOut<<<grd, blk, SMEM>>>(wo, ob, out, CDIM, 0, CHW, CHW, 1.f,
                                 bo, x, CHW, nullptr);
    }
}

// round 16
// speedup vs baseline: 1.0695x; 1.0211x over previous
#include <cuda_runtime.h>
#include <cuda_bf16.h>
#include <math.h>
#include <stdint.h>

#define BSZ 16
#define CDIM 512
#define HWD 1024   // 32*32
#define HB  8      // half batch

// ---------------- device scratch (allocation-guard safe) -------------------
__device__ __nv_bfloat16  g_xb [BSZ * CDIM * HWD];           // x bf16 [b][c][i]
__device__ __nv_bfloat16  g_qkv[BSZ * 3 * CDIM * HWD];       // q|k|v [b][3c][i]
__device__ __nv_bfloat16  g_ab [BSZ * HWD * HWD];            // unnormalized P bf16
__device__ __nv_bfloat16  g_ob [BSZ * CDIM * HWD];           // attn@V bf16 [b][c][i]
__device__ __nv_bfloat16  g_w  [4][CDIM * CDIM];             // Wq|Wk|Wv (1536x512), Wo
__device__ float          g_bqkv[3 * CDIM];                  // packed bq|bk|bv
__device__ float          g_part[BSZ * HWD * 16];            // row-sum partials
__device__ float          g_inv [BSZ * HWD];                 // 1/rowsum

// ---------------- small helpers --------------------------------------------
__device__ __forceinline__ uint32_t packbf(float lo, float hi) {
    uint32_t r;
    asm("cvt.rn.bf16x2.f32 %0, %1, %2;" : "=r"(r) : "f"(hi), "f"(lo));
    return r;
}
__device__ __forceinline__ void ldm4(uint32_t r[4], uint32_t addr) {
    asm volatile("ldmatrix.sync.aligned.m8n8.x4.shared.b16 {%0,%1,%2,%3}, [%4];"
                 : "=r"(r[0]), "=r"(r[1]), "=r"(r[2]), "=r"(r[3]) : "r"(addr));
}
__device__ __forceinline__ void ldm4t(uint32_t r[4], uint32_t addr) {
    asm volatile("ldmatrix.sync.aligned.m8n8.x4.trans.shared.b16 {%0,%1,%2,%3}, [%4];"
                 : "=r"(r[0]), "=r"(r[1]), "=r"(r[2]), "=r"(r[3]) : "r"(addr));
}
__device__ __forceinline__ void mma_bf16(float c[4], const uint32_t a[4], const uint32_t b[2]) {
    asm volatile(
        "mma.sync.aligned.m16n8k16.row.col.f32.bf16.bf16.f32 "
        "{%0,%1,%2,%3}, {%4,%5,%6,%7}, {%8,%9}, {%0,%1,%2,%3};\n"
        : "+f"(c[0]), "+f"(c[1]), "+f"(c[2]), "+f"(c[3])
        : "r"(a[0]), "r"(a[1]), "r"(a[2]), "r"(a[3]), "r"(b[0]), "r"(b[1]));
}
__device__ __forceinline__ void cpa16(uint32_t dst, const void* src) {
    asm volatile("cp.async.cg.shared.global [%0], [%1], 16;" :: "r"(dst), "l"(src));
}
#define CP_COMMIT() asm volatile("cp.async.commit_group;" ::: "memory")
#define CP_WAIT1()  asm volatile("cp.async.wait_group 1;" ::: "memory")
#define CP_WAIT0()  asm volatile("cp.async.wait_group 0;" ::: "memory")

// ---------------------------------------------------------------------------
// Fused prologue: weight cvt (4x512x512), bias pack, x cvt. One launch.
// ---------------------------------------------------------------------------
__global__ __launch_bounds__(256)
void prologue_kernel(const float4* __restrict__ x4,
                     const float4* __restrict__ w0, const float4* __restrict__ w1,
                     const float4* __restrict__ w2, const float4* __restrict__ w3,
                     const float* __restrict__ bq, const float* __restrict__ bk,
                     const float* __restrict__ bv,
                     uint2* __restrict__ xb, uint2* __restrict__ wdst,
                     float* __restrict__ bias)
{
    const int gid = blockIdx.x * 256 + threadIdx.x;

    if (gid < 3 * CDIM)
        bias[gid] = gid < CDIM ? bq[gid]
                  : gid < 2 * CDIM ? bk[gid - CDIM] : bv[gid - 2 * CDIM];

    if (gid < 4 * 65536) {                    // 4 mats x 65536 float4
        const int which = gid >> 16, i = gid & 65535;
        const float4* src = which == 0 ? w0 : which == 1 ? w1
                          : which == 2 ? w2 : w3;
        float4 v = src[i];
        uint2 o;
        o.x = packbf(v.x, v.y);
        o.y = packbf(v.z, v.w);
        wdst[gid] = o;
    }

    const int total = BSZ * CDIM * HWD / 4;   // 2097152 float4
    for (int i = gid; i < total; i += gridDim.x * 256) {
        float4 v = x4[i];
        uint2 o;
        o.x = packbf(v.x, v.y);
        o.y = packbf(v.z, v.w);
        xb[i] = o;
    }
}

// ---------------------------------------------------------------------------
// Batched bf16 tensor-core GEMM (see round-11 comments; unchanged engine).
// MODE 0: plain; MODE 1: exp()+row-sum partials; MODE 2: *1/rowsum.
// ---------------------------------------------------------------------------
template<bool A_KC, bool B_NC, int LDA, int LDB, bool BIAS, bool RESID,
         bool OUT_F32, int MODE>
__global__ __launch_bounds__(128, 2)
void gemm_bf16(const __nv_bfloat16* __restrict__ A,
               const __nv_bfloat16* __restrict__ B,
               void* __restrict__ Cv, int K,
               long baA, long baB, long baC,
               float alpha, const float* __restrict__ bias,
               const float* __restrict__ resid, long baR,
               float* __restrict__ aux)
{
    extern __shared__ uint8_t smem[];
    const uint32_t smem_u = (uint32_t)__cvta_generic_to_shared(smem);
    const int STAGE = 32768;            // 16KB A + 16KB B

    const int b = blockIdx.z;
    A += (long)b * baA;
    B += (long)b * baB;
    if (RESID) resid += (long)b * baR;

    const int tid  = threadIdx.x;
    const int lane = tid & 31;
    const int wid  = tid >> 5;          // 0..3
    const int m0   = blockIdx.y * 128;
    const int n0   = blockIdx.x * 128;
    const int wm0  = (wid >> 1) * 64;   // 0 or 64
    const int wn0  = (wid & 1) * 64;    // 0 or 64

    float acc[4][8][4];
    #pragma unroll
    for (int i = 0; i < 4; ++i)
        #pragma unroll
        for (int j = 0; j < 8; ++j)
            #pragma unroll
            for (int r = 0; r < 4; ++r) acc[i][j][r] = 0.f;

    auto fill = [&](int kt, int buf) {
        const int k0 = kt * 64;
        const uint32_t Ab = smem_u + buf * STAGE;
        const uint32_t Bb = Ab + 16384;
        #pragma unroll
        for (int i = 0; i < 8; ++i) {
            const int g = tid + i * 128;
            if (A_KC) {
                const int m = g >> 3, u = g & 7;
                cpa16(Ab + m * 128 + ((u ^ (m & 7)) << 4),
                      A + (long)(m0 + m) * LDA + k0 + u * 8);
            } else {
                const int kk = g >> 4, u = g & 15;
                cpa16(Ab + kk * 256 + ((u ^ (kk & 7)) << 4),
                      A + (long)(k0 + kk) * LDA + m0 + u * 8);
            }
            if (B_NC) {
                const int kk = g >> 4, u = g & 15;
                cpa16(Bb + kk * 256 + ((u ^ (kk & 7)) << 4),
                      B + (long)(k0 + kk) * LDB + n0 + u * 8);
            } else {
                const int n = g >> 3, u = g & 7;
                cpa16(Bb + n * 128 + ((u ^ (n & 7)) << 4),
                      B + (long)(n0 + n) * LDB + k0 + u * 8);
            }
        }
        CP_COMMIT();
    };

    auto loadB = [&](uint32_t Bb, int s, int tb, uint32_t r[4]) {
        if (B_NC) {
            const int k_row = s * 16 + (lane & 7) + ((lane >> 3) & 1) * 8;
            const int u = ((wn0 + tb * 16) >> 3) + ((lane >> 4) & 1);
            ldm4t(r, Bb + k_row * 256 + ((u ^ (k_row & 7)) << 4));
        } else {
            const int n_row = wn0 + tb * 16 + (lane & 7) + ((lane >> 4) & 1) * 8;
            const int u = 2 * s + ((lane >> 3) & 1);
            ldm4(r, Bb + n_row * 128 + ((u ^ (n_row & 7)) << 4));
        }
    };

    auto compute = [&](int buf) {
        const uint32_t Ab = smem_u + buf * STAGE;
        const uint32_t Bb = Ab + 16384;
        #pragma unroll
        for (int s = 0; s < 4; ++s) {
            uint32_t af[4][4];
            #pragma unroll
            for (int tm = 0; tm < 4; ++tm) {
                if (A_KC) {
                    const int m_row = wm0 + tm * 16 + (lane & 15);
                    const int u = 2 * s + (lane >> 4);
                    ldm4(af[tm], Ab + m_row * 128 + ((u ^ (m_row & 7)) << 4));
                } else {
                    const int k_row = s * 16 + (lane & 7) + ((lane >> 4) & 1) * 8;
                    const int u = ((wm0 + tm * 16) >> 3) + ((lane >> 3) & 1);
                    ldm4t(af[tm], Ab + k_row * 256 + ((u ^ (k_row & 7)) << 4));
                }
            }
            uint32_t rb[2][4];
            loadB(Bb, s, 0, rb[0]);
            #pragma unroll
            for (int tb = 0; tb < 4; ++tb) {
                if (tb < 3) loadB(Bb, s, tb + 1, rb[(tb + 1) & 1]);
                const uint32_t* r = rb[tb & 1];
                uint32_t b0[2] = { r[0], r[1] };
                uint32_t b1[2] = { r[2], r[3] };
                #pragma unroll
                for (int tm = 0; tm < 4; ++tm) {
                    mma_bf16(acc[tm][tb * 2],     af[tm], b0);
                    mma_bf16(acc[tm][tb * 2 + 1], af[tm], b1);
                }
            }
        }
    };

    const int nkt = K >> 6;
    fill(0, 0);
    if (nkt > 1) fill(1, 1);

    for (int kt = 0; kt < nkt; ++kt) {
        if (kt == nkt - 1) { CP_WAIT0(); } else { CP_WAIT1(); }
        __syncthreads();
        if (kt + 2 < nkt) fill(kt + 2, (kt + 2) % 3);
        compute(kt % 3);
    }

    // ---- epilogue ----
    const int kq = lane & 3;
    const int mq = lane >> 2;

    float invs[16];
    if (MODE == 2) {
        #pragma unroll
        for (int tn = 0; tn < 8; ++tn) {
            const int n = n0 + wn0 + tn * 8 + 2 * kq;
            invs[tn * 2]     = aux[(long)b * HWD + n];
            invs[tn * 2 + 1] = aux[(long)b * HWD + n + 1];
        }
    }

    #pragma unroll
    for (int tm = 0; tm < 4; ++tm) {
        const int mA = m0 + wm0 + tm * 16 + mq;
        const int mB = mA + 8;
        if (MODE == 1) {
            __nv_bfloat16* C = (__nv_bfloat16*)Cv + (long)b * baC;
            float sA = 0.f, sB = 0.f;
            #pragma unroll
            for (int tn = 0; tn < 8; ++tn) {
                const int n = n0 + wn0 + tn * 8 + 2 * kq;
                float e0 = __expf(alpha * acc[tm][tn][0]);
                float e1 = __expf(alpha * acc[tm][tn][1]);
                float e2 = __expf(alpha * acc[tm][tn][2]);
                float e3 = __expf(alpha * acc[tm][tn][3]);
                sA += e0 + e1;
                sB += e2 + e3;
                *(uint32_t*)&C[(long)mA * HWD + n] = packbf(e0, e1);
                *(uint32_t*)&C[(long)mB * HWD + n] = packbf(e2, e3);
            }
            sA += __shfl_xor_sync(0xFFFFFFFFu, sA, 1);
            sA += __shfl_xor_sync(0xFFFFFFFFu, sA, 2);
            sB += __shfl_xor_sync(0xFFFFFFFFu, sB, 1);
            sB += __shfl_xor_sync(0xFFFFFFFFu, sB, 2);
            if (kq == 0) {
                const int jt2 = blockIdx.x * 2 + (wid & 1);
                aux[((long)b * HWD + mA) * 16 + jt2] = sA;
                aux[((long)b * HWD + mB) * 16 + jt2] = sB;
            }
        } else {
            const float biA = BIAS ? bias[mA] : 0.f;
            const float biB = BIAS ? bias[mB] : 0.f;
            #pragma unroll
            for (int tn = 0; tn < 8; ++tn) {
                const int n = n0 + wn0 + tn * 8 + 2 * kq;
                float v0 = alpha * acc[tm][tn][0] + biA;
                float v1 = alpha * acc[tm][tn][1] + biA;
                float v2 = alpha * acc[tm][tn][2] + biB;
                float v3 = alpha * acc[tm][tn][3] + biB;
                if (MODE == 2) {
                    v0 *= invs[tn * 2];     v1 *= invs[tn * 2 + 1];
                    v2 *= invs[tn * 2];     v3 *= invs[tn * 2 + 1];
                }
                if (RESID) {
                    const float2 rA = *(const float2*)&resid[(long)mA * HWD + n];
                    const float2 rB = *(const float2*)&resid[(long)mB * HWD + n];
                    v0 += rA.x; v1 += rA.y; v2 += rB.x; v3 += rB.y;
                }
                if (OUT_F32) {
                    float* C = (float*)Cv + (long)b * baC;
                    *(float2*)&C[(long)mA * HWD + n] = make_float2(v0, v1);
                    *(float2*)&C[(long)mB * HWD + n] = make_float2(v2, v3);
                } else {
                    __nv_bfloat16* C = (__nv_bfloat16*)Cv + (long)b * baC;
                    *(uint32_t*)&C[(long)mA * HWD + n] = packbf(v0, v1);
                    *(uint32_t*)&C[(long)mB * HWD + n] = packbf(v2, v3);
                }
            }
        }
    }
}

// Reduce 16 partials per row -> 1/rowsum over nrows rows.
__global__ __launch_bounds__(256)
void rowsum_inv_kernel(const float4* __restrict__ part, float* __restrict__ inv)
{
    const int i = blockIdx.x * 256 + threadIdx.x;
    float4 a = part[i * 4 + 0];
    float4 b = part[i * 4 + 1];
    float4 c = part[i * 4 + 2];
    float4 d = part[i * 4 + 3];
    float s = (a.x + a.y + a.z + a.w) + (b.x + b.y + b.z + b.w)
            + (c.x + c.y + c.z + c.w) + (d.x + d.y + d.z + d.w);
    inv[i] = 1.f / s;
}

// ---------------------------------------------------------------------------
extern "C" void kernel_launch(void* const* d_in, const int* in_sizes, int n_in,
                              void* d_out, int out_size)
{
    const float* x  = (const float*)d_in[0];
    const float* Wq = (const float*)d_in[1];
    const float* bq = (const float*)d_in[2];
    const float* Wk = (const float*)d_in[3];
    const float* bk = (const float*)d_in[4];
    const float* Wv = (const float*)d_in[5];
    const float* bv = (const float*)d_in[6];
    const float* Wo = (const float*)d_in[7];
    const float* bo = (const float*)d_in[8];
    float* out = (float*)d_out;

    float *bqkv, *part, *inv;
    __nv_bfloat16 *xb, *qkv, *ab, *ob, *wbase;
    cudaGetSymbolAddress((void**)&xb,   g_xb);
    cudaGetSymbolAddress((void**)&qkv,  g_qkv);
    cudaGetSymbolAddress((void**)&ab,   g_ab);
    cudaGetSymbolAddress((void**)&ob,   g_ob);
    cudaGetSymbolAddress((void**)&wbase, g_w);
    cudaGetSymbolAddress((void**)&bqkv, g_bqkv);
    cudaGetSymbolAddress((void**)&part, g_part);
    cudaGetSymbolAddress((void**)&inv,  g_inv);
    __nv_bfloat16* wqkv = wbase;                     // Wq|Wk|Wv = [1536][512]
    __nv_bfloat16* wo   = wbase + 3 * CDIM * CDIM;

    const long CHW  = (long)CDIM * HWD;
    const long QKVB = 3 * CHW;
    const long SHW  = (long)HWD * HWD;
    const int  SMEM = 3 * 32768;
    const dim3 blk(128);

    // half-batch offsets
    const long oXB  = (long)HB * CHW;        // xb, ob, out, x (resid)
    const long oQKV = (long)HB * QKVB;       // qkv
    const long oAB  = (long)HB * SHW;        // ab
    const long oPT  = (long)HB * HWD * 16;   // part
    const long oIV  = (long)HB * HWD;        // inv

    auto kProj  = gemm_bf16<true,  true,  CDIM, HWD, true,  false, false, 0>;
    auto kScore = gemm_bf16<false, true,  HWD,  HWD, false, false, false, 1>;
    auto kAV    = gemm_bf16<true,  false, HWD,  HWD, false, false, false, 2>;
    auto kOut   = gemm_bf16<true,  true,  CDIM, HWD, true,  true,  true,  0>;
    cudaFuncSetAttribute(kProj,  cudaFuncAttributeMaxDynamicSharedMemorySize, SMEM);
    cudaFuncSetAttribute(kScore, cudaFuncAttributeMaxDynamicSharedMemorySize, SMEM);
    cudaFuncSetAttribute(kAV,    cudaFuncAttributeMaxDynamicSharedMemorySize, SMEM);
    cudaFuncSetAttribute(kOut,   cudaFuncAttributeMaxDynamicSharedMemorySize, SMEM);

    // Fork/join plumbing: created ONCE during the uncaptured correctness call;
    // reused and never destroyed. All s1 work uses stream handle 0 (the same
    // default stream <<<>>> resolves to); s2 is pulled into the capture via
    // fork events and joined back before return.
    static cudaStream_t s2 = nullptr;
    static cudaEvent_t evP = nullptr, evQK0 = nullptr, evV = nullptr,
                       evEnd = nullptr;
    if (s2 == nullptr) {
        cudaStreamCreateWithFlags(&s2, cudaStreamNonBlocking);
        cudaEventCreateWithFlags(&evP,   cudaEventDisableTiming);
        cudaEventCreateWithFlags(&evQK0, cudaEventDisableTiming);
        cudaEventCreateWithFlags(&evV,   cudaEventDisableTiming);
        cudaEventCreateWithFlags(&evEnd, cudaEventDisableTiming);
    }

    // 0) prologue (s1)
    prologue_kernel<<<2048, 256>>>((const float4*)x,
                                   (const float4*)Wq, (const float4*)Wk,
                                   (const float4*)Wv, (const float4*)Wo,
                                   bq, bk, bv,
                                   (uint2*)xb, (uint2*)wbase, bqkv);
    cudaEventRecord(evP, 0);
    cudaStreamWaitEvent(s2, evP, 0);

    // s2: V projection (all batches)
    {
        dim3 grd(HWD / 128, CDIM / 128, BSZ);
        kProj<<<grd, blk, SMEM, s2>>>(wqkv + (long)2 * CDIM * CDIM, xb,
                                      qkv + 2 * CHW, CDIM, 0, CHW, QKVB,
                                      1.f, bqkv + 2 * CDIM, nullptr, 0, nullptr);
        cudaEventRecord(evV, s2);
    }

    // s1: QK projection, chunk 0 (batches 0..7)
    {
        dim3 grd(HWD / 128, 2 * CDIM / 128, HB);
        kProj<<<grd, blk, SMEM>>>(wqkv, xb, qkv, CDIM, 0, CHW, QKVB,
                                  1.f, bqkv, nullptr, 0, nullptr);
    }
    cudaEventRecord(evQK0, 0);
    cudaStreamWaitEvent(s2, evQK0, 0);

    // s2 pipeline for chunk 0: scores -> rowsum -> AV -> out
    {
        dim3 grdS(HWD / 128, HWD / 128, HB);
        const float alpha = 1.0f / sqrtf((float)CDIM);
        kScore<<<grdS, blk, SMEM, s2>>>(qkv, qkv + CHW, ab, CDIM,
                                        QKVB, QKVB, SHW,
                                        alpha, nullptr, nullptr, 0, part);
        rowsum_inv_kernel<<<HB * HWD / 256, 256, 0, s2>>>((const float4*)part, inv);
        dim3 grdA(HWD / 128, CDIM / 128, HB);
        kAV<<<grdA, blk, SMEM, s2>>>(qkv + 2 * CHW, ab, ob, HWD,
                                     QKVB, SHW, CHW,
                                     1.f, nullptr, nullptr, 0, inv);
        kOut<<<grdA, blk, SMEM, s2>>>(wo, ob, out, CDIM, 0, CHW, CHW,
                                      1.f, bo, x, CHW, nullptr);
        cudaEventRecord(evEnd, s2);
    }

    // s1: QK projection chunk 1, then its pipeline (overlaps s2 chunk 0)
    {
        dim3 grd(HWD / 128, 2 * CDIM / 128, HB);
        kProj<<<grd, blk, SMEM>>>(wqkv, xb + oXB, qkv + oQKV, CDIM,
                                  0, CHW, QKVB,
                                  1.f, bqkv, nullptr, 0, nullptr);
    }
    {
        dim3 grdS(HWD / 128, HWD / 128, HB);
        const float alpha = 1.0f / sqrtf((float)CDIM);
        kScore<<<grdS, blk, SMEM>>>(qkv + oQKV, qkv + oQKV + CHW, ab + oAB,
                                    CDIM, QKVB, QKVB, SHW,
                                    alpha, nullptr, nullptr, 0, part + oPT);
        rowsum_inv_kernel<<<HB * HWD / 256, 256>>>((const float4*)(part + oPT),
                                                   inv + oIV);
    }
    cudaStreamWaitEvent((cudaStream_t)0, evV, 0);   // AV_c1 needs V
    {
        dim3 grdA(HWD / 128, CDIM / 128, HB);
        kAV<<<grdA, blk, SMEM>>>(qkv + oQKV + 2 * CHW, ab + oAB, ob + oXB, HWD,
                                 QKVB, SHW, CHW,
                                 1.f, nullptr, nullptr, 0, inv + oIV);
        kOut<<<grdA, blk, SMEM>>>(wo, ob + oXB, out + oXB, CDIM, 0, CHW, CHW,
                                  1.f, bo, x + oXB, CHW, nullptr);
    }

    // Join s2 back into s1 before capture ends.
    cudaStreamWaitEvent((cudaStream_t)0, evEnd, 0);
}